// round 4
// baseline (speedup 1.0000x reference)
#include <cuda_runtime.h>

// ProjectionLoss fused single-kernel, issue-count-optimized.
//   prepass: fold K into gt [R|t] and cam_preds; store per (b,v) a 128B record:
//            [0..7]  uv_gt   : (u0,v0)(u1,v1)(u2,v2)(uc,vc)   (K@R cols, K@t)
//            [8..15] uv_pred : same with cam_preds
//            [16..23] w_pair : (gw0,pw0)(gw1,pw1)(gw2,pw2)(gwc,pwc)
//            [24..31] pad
//   main: per (b,j) thread, 8 views: 9x fma.rn.f32x2 matvec, scalar epilogue
//         with ONE rcp per view, min()-form smooth-MSE (no branches/selects).
//   tail: last-arriving block reduces per-block partials in fixed order.

#define B_TOTAL 16384
#define V_NUM   8
#define J_NUM   64
#define NB      8
#define THREADS (NB * J_NUM)          // 512
#define NBLOCKS (B_TOTAL / NB)        // 2048

#define POW_CONST 219.7120972f        // 400^0.9

__device__ float g_partials[NBLOCKS];
__device__ int   g_count = 0;

typedef unsigned long long u64;

__device__ __forceinline__ u64 pk2(float lo, float hi) {
    u64 r; asm("mov.b64 %0, {%1, %2};" : "=l"(r) : "f"(lo), "f"(hi)); return r;
}
__device__ __forceinline__ void upk2(float& lo, float& hi, u64 v) {
    asm("mov.b64 {%0, %1}, %2;" : "=f"(lo), "=f"(hi) : "l"(v));
}
__device__ __forceinline__ u64 fma2(u64 a, u64 b, u64 c) {
    u64 d; asm("fma.rn.f32x2 %0, %1, %2, %3;" : "=l"(d) : "l"(a), "l"(b), "l"(c)); return d;
}
__device__ __forceinline__ float rcpa(float x) {
    float r; asm("rcp.approx.f32 %0, %1;" : "=f"(r) : "f"(x)); return r;
}
__device__ __forceinline__ float lg2a(float x) {
    float r; asm("lg2.approx.f32 %0, %1;" : "=f"(r) : "f"(x)); return r;
}
__device__ __forceinline__ float ex2a(float x) {
    float r; asm("ex2.approx.f32 %0, %1;" : "=f"(r) : "f"(x)); return r;
}
__device__ __forceinline__ float smooth_term(float d2) {
    // exact rewrite of: d2>400 ? d2^0.1 * 400^0.9 : d2   (pow-branch >= d2 iff d2<=400)
    float p = ex2a(lg2a(d2) * 0.1f) * POW_CONST;
    return fminf(d2, p);
}

__global__ __launch_bounds__(THREADS)
void proj_loss_fused(const float* __restrict__ gt_kps,
                     const float* __restrict__ pr_kps,
                     const float* __restrict__ gt_R,
                     const float* __restrict__ gt_t,
                     const float* __restrict__ Kmat,
                     const float* __restrict__ cam,
                     float* __restrict__ out)
{
    __shared__ __align__(16) float sGT[NB * J_NUM * 3];     // 1536
    __shared__ __align__(16) float sPR[NB * J_NUM * 3];     // 1536
    __shared__ __align__(16) float sR [NB * V_NUM * 9];     // 576
    __shared__ __align__(16) float sT [NB * V_NUM * 3];     // 192
    __shared__ __align__(16) float sC [NB * V_NUM * 12];    // 768
    __shared__ float sK[V_NUM * 9];                         // 72
    __shared__ __align__(16) float sFold[NB * V_NUM * 32];  // 2048 (128B per (b,v))
    __shared__ float sWarp[THREADS / 32];
    __shared__ int   sIsLast;

    const int tid = threadIdx.x;
    const long b0 = (long)blockIdx.x * NB;

    // ---- cooperative float4 staged loads ----
    {
        const float4* g = (const float4*)(gt_kps + b0 * (J_NUM * 3));
        float4* s = (float4*)sGT;
        for (int i = tid; i < NB * J_NUM * 3 / 4; i += THREADS) s[i] = g[i];
    }
    {
        const float4* g = (const float4*)(pr_kps + b0 * (J_NUM * 3));
        float4* s = (float4*)sPR;
        for (int i = tid; i < NB * J_NUM * 3 / 4; i += THREADS) s[i] = g[i];
    }
    {
        const float4* g = (const float4*)(gt_R + b0 * (V_NUM * 9));
        float4* s = (float4*)sR;
        for (int i = tid; i < NB * V_NUM * 9 / 4; i += THREADS) s[i] = g[i];
    }
    {
        const float4* g = (const float4*)(gt_t + b0 * (V_NUM * 3));
        float4* s = (float4*)sT;
        for (int i = tid; i < NB * V_NUM * 3 / 4; i += THREADS) s[i] = g[i];
    }
    {
        const float4* g = (const float4*)(cam + b0 * (V_NUM * 12));
        float4* s = (float4*)sC;
        for (int i = tid; i < NB * V_NUM * 12 / 4; i += THREADS) s[i] = g[i];
    }
    if (tid < V_NUM * 9) sK[tid] = Kmat[tid];
    __syncthreads();

    // ---- prepass: fold K; pow-of-2 index math only ----
    #pragma unroll
    for (int rep = 0; rep < 4; rep++) {
        int idx = tid + rep * THREADS;      // 0..2047
        int g   = idx >> 5;                 // (bl,v) group, 0..63
        int el  = idx & 31;
        if (el < 24) {
            int bl = g >> 3;
            int v  = g & 7;
            int which, c, krow;
            if (el < 16) { which = el >> 3; c = (el & 7) >> 1; krow = el & 1; }
            else         { c = (el - 16) >> 1; which = el & 1; krow = 2;      }
            const float* k = &sK[v * 9 + krow * 3];
            float val;
            if (which == 0) {
                if (c < 3) {
                    const float* R = &sR[bl * 72 + v * 9];
                    val = fmaf(k[0], R[c], fmaf(k[1], R[3 + c], k[2] * R[6 + c]));
                } else {
                    const float* t = &sT[bl * 24 + v * 3];
                    val = fmaf(k[0], t[0], fmaf(k[1], t[1], k[2] * t[2]));
                }
            } else {
                const float* cm = &sC[bl * 96 + v * 12];
                val = fmaf(k[0], cm[c], fmaf(k[1], cm[4 + c], k[2] * cm[8 + c]));
            }
            sFold[(g << 5) + el] = val;
        }
    }
    __syncthreads();

    // ---- main: one thread = (b_local, j), 8 views ----
    const int bl = tid >> 6;
    const int j  = tid & 63;

    const float X0 = sGT[bl * 192 + j * 3 + 0];
    const float X1 = sGT[bl * 192 + j * 3 + 1];
    const float X2 = sGT[bl * 192 + j * 3 + 2];
    const float P0 = sPR[bl * 192 + j * 3 + 0];
    const float P1 = sPR[bl * 192 + j * 3 + 1];
    const float P2 = sPR[bl * 192 + j * 3 + 2];

    const u64 XX0 = pk2(X0, X0), XX1 = pk2(X1, X1), XX2 = pk2(X2, X2);
    const u64 PP0 = pk2(P0, P0), PP1 = pk2(P1, P1), PP2 = pk2(P2, P2);
    const u64 XP0 = pk2(X0, P0), XP1 = pk2(X1, P1), XP2 = pk2(X2, P2);

    const ulonglong2* sF2 = (const ulonglong2*)sFold;   // 8 x 16B slots per (bl,v)

    float accx = 0.0f, accy = 0.0f;

    #pragma unroll
    for (int v = 0; v < V_NUM; v++) {
        const int base = (bl * 8 + v) * 4;
        const ulonglong2 a = sF2[base * 2 + 0]; // uv_gt cols 0,1
        const ulonglong2 b = sF2[base * 2 + 1]; // uv_gt cols 2,const
        const ulonglong2 c = sF2[base * 2 + 2]; // uv_pred cols 0,1
        const ulonglong2 d = sF2[base * 2 + 3]; // uv_pred cols 2,const
        const ulonglong2 e = sF2[base * 2 + 4]; // w_pair cols 0,1
        const ulonglong2 f = sF2[base * 2 + 5]; // w_pair cols 2,const

        u64 uv  = fma2(a.x, XX0, fma2(a.y, XX1, fma2(b.x, XX2, b.y)));
        u64 upv = fma2(c.x, PP0, fma2(c.y, PP1, fma2(d.x, PP2, d.y)));
        u64 w2  = fma2(e.x, XP0, fma2(e.y, XP1, fma2(f.x, XP2, f.y)));

        float w, wp;  upk2(w, wp, w2);
        float u, vv;  upk2(u, vv, uv);
        float up, vp; upk2(up, vp, upv);

        float r  = rcpa(w * wp);
        float nw = -w;
        float dx = fmaf(up, nw, u  * wp) * r;
        float dy = fmaf(vp, nw, vv * wp) * r;

        accx += smooth_term(dx * dx);
        accy += smooth_term(dy * dy);
    }

    float acc = accx + accy;

    // ---- block reduction ----
    #pragma unroll
    for (int o = 16; o > 0; o >>= 1)
        acc += __shfl_xor_sync(0xFFFFFFFFu, acc, o);

    const int lane = tid & 31;
    const int wid  = tid >> 5;
    if (lane == 0) sWarp[wid] = acc;
    __syncthreads();

    if (wid == 0) {
        float s = (lane < THREADS / 32) ? sWarp[lane] : 0.0f;
        #pragma unroll
        for (int o = 8; o > 0; o >>= 1)
            s += __shfl_xor_sync(0xFFFFFFFFu, s, o);
        if (lane == 0) g_partials[blockIdx.x] = s;
    }

    // ---- fused finish: last block reduces partials (fixed order) ----
    __threadfence();
    if (tid == 0) {
        int cnum = atomicAdd(&g_count, 1);
        sIsLast = (cnum == NBLOCKS - 1);
    }
    __syncthreads();

    if (sIsLast) {
        float s = 0.0f;
        #pragma unroll
        for (int rep = 0; rep < NBLOCKS / THREADS; rep++)
            s += g_partials[tid + rep * THREADS];

        #pragma unroll
        for (int o = 16; o > 0; o >>= 1)
            s += __shfl_xor_sync(0xFFFFFFFFu, s, o);
        if (lane == 0) sWarp[wid] = s;
        __syncthreads();

        if (wid == 0) {
            float t = (lane < THREADS / 32) ? sWarp[lane] : 0.0f;
            #pragma unroll
            for (int o = 8; o > 0; o >>= 1)
                t += __shfl_xor_sync(0xFFFFFFFFu, t, o);
            if (lane == 0) {
                out[0] = t * (1.0f / (2.0f * (float)B_TOTAL));
                g_count = 0;   // reset for next graph replay
            }
        }
    }
}

extern "C" void kernel_launch(void* const* d_in, const int* in_sizes, int n_in,
                              void* d_out, int out_size)
{
    const float* gt_kps = (const float*)d_in[0];
    const float* pr_kps = (const float*)d_in[1];
    const float* gt_R   = (const float*)d_in[2];
    const float* gt_t   = (const float*)d_in[3];
    const float* Kmat   = (const float*)d_in[4];
    const float* cam    = (const float*)d_in[5];
    float* out = (float*)d_out;

    proj_loss_fused<<<NBLOCKS, THREADS>>>(gt_kps, pr_kps, gt_R, gt_t, Kmat, cam, out);
}

// round 6
// speedup vs baseline: 1.4885x; 1.4885x over previous
#include <cuda_runtime.h>

// ProjectionLoss fused single-kernel, LSU-minimized mapping:
//   thread = (b_local, view). Folded K@[R|t] and K@cam live in REGISTERS,
//   built once per thread. j-loop unrolled x4 reads keypoints with LDS.128
//   from raw contiguous smem (1.5 LDS per point-view).
//   Smooth-MSE in min() form (branch-free), one rcp per point-view.
//   Tail: last-arriving block reduces per-block partials in fixed order.

#define B_TOTAL 16384
#define V_NUM   8
#define J_NUM   64
#define NB      16                      // batch elements per block
#define THREADS (NB * V_NUM)            // 128
#define NBLOCKS (B_TOTAL / NB)          // 1024

#define POW_CONST 219.7120972f          // 400^0.9

__device__ float g_partials[NBLOCKS];
__device__ int   g_count = 0;

__device__ __forceinline__ float rcpa(float x) {
    float r; asm("rcp.approx.f32 %0, %1;" : "=f"(r) : "f"(x)); return r;
}
__device__ __forceinline__ float lg2a(float x) {
    float r; asm("lg2.approx.f32 %0, %1;" : "=f"(r) : "f"(x)); return r;
}
__device__ __forceinline__ float ex2a(float x) {
    float r; asm("ex2.approx.f32 %0, %1;" : "=f"(r) : "f"(x)); return r;
}
__device__ __forceinline__ float smooth_term(float d2) {
    // exact rewrite of: d2>400 ? d2^0.1 * 400^0.9 : d2  (pow branch >= d2 iff d2<=400)
    float p = ex2a(lg2a(d2) * 0.1f) * POW_CONST;
    return fminf(d2, p);
}

__global__ __launch_bounds__(THREADS, 8)
void proj_loss_fused(const float* __restrict__ gt_kps,
                     const float* __restrict__ pr_kps,
                     const float* __restrict__ gt_R,
                     const float* __restrict__ gt_t,
                     const float* __restrict__ Kmat,
                     const float* __restrict__ cam,
                     float* __restrict__ out)
{
    __shared__ __align__(16) float sGT[NB * J_NUM * 3];   // 12288 B
    __shared__ __align__(16) float sPR[NB * J_NUM * 3];   // 12288 B
    __shared__ __align__(16) float sR [NB * V_NUM * 9];   // 4608 B
    __shared__ __align__(16) float sT [NB * V_NUM * 3];   // 1536 B
    __shared__ __align__(16) float sC [NB * V_NUM * 12];  // 6144 B
    __shared__ float sK[V_NUM * 9];                       // 288 B
    __shared__ float sWarp[THREADS / 32];
    __shared__ int   sIsLast;

    const int tid = threadIdx.x;
    const long b0 = (long)blockIdx.x * NB;

    // ---- cooperative float4 staged loads (guarded strided loops) ----
    {
        const float4* g = (const float4*)(gt_kps + b0 * (J_NUM * 3));
        float4* s = (float4*)sGT;
        #pragma unroll
        for (int i = tid; i < NB * J_NUM * 3 / 4; i += THREADS) s[i] = g[i];
    }
    {
        const float4* g = (const float4*)(pr_kps + b0 * (J_NUM * 3));
        float4* s = (float4*)sPR;
        #pragma unroll
        for (int i = tid; i < NB * J_NUM * 3 / 4; i += THREADS) s[i] = g[i];
    }
    {
        const float4* g = (const float4*)(gt_R + b0 * (V_NUM * 9));
        float4* s = (float4*)sR;
        #pragma unroll
        for (int i = tid; i < NB * V_NUM * 9 / 4; i += THREADS) s[i] = g[i];
    }
    {
        const float4* g = (const float4*)(gt_t + b0 * (V_NUM * 3));
        float4* s = (float4*)sT;
        #pragma unroll
        for (int i = tid; i < NB * V_NUM * 3 / 4; i += THREADS) s[i] = g[i];
    }
    {
        const float4* g = (const float4*)(cam + b0 * (V_NUM * 12));
        float4* s = (float4*)sC;
        #pragma unroll
        for (int i = tid; i < NB * V_NUM * 12 / 4; i += THREADS) s[i] = g[i];
    }
    if (tid < V_NUM * 9) sK[tid] = Kmat[tid];
    __syncthreads();

    // ---- per-thread: fold K into [R|t] (gt) and cam (pred), keep in regs ----
    const int bl = tid >> 3;     // 0..15
    const int v  = tid & 7;      // 0..7

    float G[12];   // gt  folded 3x4: rows of K@R | K@t
    float Cm[12];  // pred folded 3x4: K@cam
    {
        const float* k  = &sK[v * 9];
        const float* R  = &sR[bl * (V_NUM * 9) + v * 9];
        const float* t  = &sT[bl * (V_NUM * 3) + v * 3];
        const float* cm = &sC[bl * (V_NUM * 12) + v * 12];
        #pragma unroll
        for (int r = 0; r < 3; r++) {
            float k0 = k[r * 3 + 0], k1 = k[r * 3 + 1], k2 = k[r * 3 + 2];
            #pragma unroll
            for (int c = 0; c < 3; c++)
                G[r * 4 + c] = fmaf(k0, R[c], fmaf(k1, R[3 + c], k2 * R[6 + c]));
            G[r * 4 + 3] = fmaf(k0, t[0], fmaf(k1, t[1], k2 * t[2]));
            #pragma unroll
            for (int c = 0; c < 4; c++)
                Cm[r * 4 + c] = fmaf(k0, cm[c], fmaf(k1, cm[4 + c], k2 * cm[8 + c]));
        }
    }

    const float4* gt4 = (const float4*)(sGT + bl * (J_NUM * 3));  // 48 float4
    const float4* pr4 = (const float4*)(sPR + bl * (J_NUM * 3));

    float acc = 0.0f;

    // ---- main loop: 64 joints, unrolled x4 (12 floats = 3 LDS.128 each side) ----
    #pragma unroll 4
    for (int jq = 0; jq < J_NUM / 4; jq++) {
        const float4 xa = gt4[jq * 3 + 0];
        const float4 xb = gt4[jq * 3 + 1];
        const float4 xc = gt4[jq * 3 + 2];
        const float4 pa = pr4[jq * 3 + 0];
        const float4 pb = pr4[jq * 3 + 1];
        const float4 pc = pr4[jq * 3 + 2];

        float Xs[4][3] = {{xa.x, xa.y, xa.z}, {xa.w, xb.x, xb.y},
                          {xb.z, xb.w, xc.x}, {xc.y, xc.z, xc.w}};
        float Ps[4][3] = {{pa.x, pa.y, pa.z}, {pa.w, pb.x, pb.y},
                          {pb.z, pb.w, pc.x}, {pc.y, pc.z, pc.w}};

        #pragma unroll
        for (int s = 0; s < 4; s++) {
            const float X0 = Xs[s][0], X1 = Xs[s][1], X2 = Xs[s][2];
            const float P0 = Ps[s][0], P1 = Ps[s][1], P2 = Ps[s][2];

            float u  = fmaf(G[0], X0, fmaf(G[1], X1, fmaf(G[2],  X2, G[3])));
            float vv = fmaf(G[4], X0, fmaf(G[5], X1, fmaf(G[6],  X2, G[7])));
            float w  = fmaf(G[8], X0, fmaf(G[9], X1, fmaf(G[10], X2, G[11])));

            float up = fmaf(Cm[0], P0, fmaf(Cm[1], P1, fmaf(Cm[2],  P2, Cm[3])));
            float vp = fmaf(Cm[4], P0, fmaf(Cm[5], P1, fmaf(Cm[6],  P2, Cm[7])));
            float wp = fmaf(Cm[8], P0, fmaf(Cm[9], P1, fmaf(Cm[10], P2, Cm[11])));

            // dx = u/w - up/wp = (u*wp - up*w) * rcp(w*wp): one MUFU rcp per point
            float r  = rcpa(w * wp);
            float nw = -w;
            float dx = fmaf(up, nw, u  * wp) * r;
            float dy = fmaf(vp, nw, vv * wp) * r;

            acc += smooth_term(dx * dx);
            acc += smooth_term(dy * dy);
        }
    }

    // ---- block reduction (4 warps) ----
    #pragma unroll
    for (int o = 16; o > 0; o >>= 1)
        acc += __shfl_xor_sync(0xFFFFFFFFu, acc, o);

    const int lane = tid & 31;
    const int wid  = tid >> 5;
    if (lane == 0) sWarp[wid] = acc;
    __syncthreads();

    if (wid == 0) {
        float s = (lane < THREADS / 32) ? sWarp[lane] : 0.0f;
        #pragma unroll
        for (int o = 2; o > 0; o >>= 1)
            s += __shfl_xor_sync(0xFFFFFFFFu, s, o);
        if (lane == 0) g_partials[blockIdx.x] = s;
    }

    // ---- fused finish: last-arriving block reduces partials (fixed order) ----
    __threadfence();
    if (tid == 0) {
        int c = atomicAdd(&g_count, 1);
        sIsLast = (c == NBLOCKS - 1);
    }
    __syncthreads();

    if (sIsLast) {
        float s = 0.0f;
        #pragma unroll
        for (int rep = 0; rep < NBLOCKS / THREADS; rep++)
            s += g_partials[tid + rep * THREADS];

        #pragma unroll
        for (int o = 16; o > 0; o >>= 1)
            s += __shfl_xor_sync(0xFFFFFFFFu, s, o);
        if (lane == 0) sWarp[wid] = s;
        __syncthreads();

        if (wid == 0) {
            float t = (lane < THREADS / 32) ? sWarp[lane] : 0.0f;
            #pragma unroll
            for (int o = 2; o > 0; o >>= 1)
                t += __shfl_xor_sync(0xFFFFFFFFu, t, o);
            if (lane == 0) {
                out[0] = t * (1.0f / (2.0f * (float)B_TOTAL));
                g_count = 0;   // reset for next graph replay
            }
        }
    }
}

extern "C" void kernel_launch(void* const* d_in, const int* in_sizes, int n_in,
                              void* d_out, int out_size)
{
    const float* gt_kps = (const float*)d_in[0];
    const float* pr_kps = (const float*)d_in[1];
    const float* gt_R   = (const float*)d_in[2];
    const float* gt_t   = (const float*)d_in[3];
    const float* Kmat   = (const float*)d_in[4];
    const float* cam    = (const float*)d_in[5];
    float* out = (float*)d_out;

    proj_loss_fused<<<NBLOCKS, THREADS>>>(gt_kps, pr_kps, gt_R, gt_t, Kmat, cam, out);
}